// round 3
// baseline (speedup 1.0000x reference)
#include <cuda_runtime.h>

#define TT 512
#define BB 128
#define II 512
#define HH 1024
#define OO 512
#define KK 32
#define G3 (3 * HH)
#define NBLK 128
#define NTHR 256

// ---------------- scratch (static device globals; allocation-free) ----------
__device__ float g_xg[(size_t)BB * TT * G3];     // (B,T,3H) input projections
__device__ float g_Hall[(size_t)TT * BB * HH];   // (T,B,H) all hidden states
__device__ float g_ring[(size_t)KK * BB * HH];   // ring buffer of last 32 h's
__device__ float g_hg[(size_t)BB * G3];          // per-step gate GEMM output
__device__ float g_w[KK * HH];                   // flipped fractional-memory weights
__device__ unsigned int g_barrier;

// ---------------- lag-weight precompute -------------------------------------
__global__ void compute_w_kernel(const float* __restrict__ mem_para) {
    int h = blockIdx.x * blockDim.x + threadIdx.x;
    if (h >= HH) return;
    float d = 0.5f / (1.0f + expf(-mem_para[h]));
    float cum = 1.0f;
    for (int k = 0; k < KK; k++) {
        cum *= ((float)k - d) / ((float)k + 1.0f);
        g_w[(KK - 1 - k) * HH + h] = cum;   // flipped: last row = most recent lag
    }
}

// zero ring + reset grid barrier (deterministic per replay)
__global__ void init_kernel() {
    size_t n = (size_t)KK * BB * HH;
    size_t i = (size_t)blockIdx.x * blockDim.x + threadIdx.x;
    size_t stride = (size_t)gridDim.x * blockDim.x;
    for (; i < n; i += stride) g_ring[i] = 0.0f;
    if (blockIdx.x == 0 && threadIdx.x == 0) g_barrier = 0u;
}

__global__ void copy_kernel(const float* __restrict__ src, float* __restrict__ dst, size_t n) {
    size_t i = (size_t)blockIdx.x * blockDim.x + threadIdx.x;
    size_t stride = (size_t)gridDim.x * blockDim.x;
    for (; i < n; i += stride) dst[i] = src[i];
}

// ---------------- generic fp32 NT GEMM: C = A(MxK) * B(NxK)^T ---------------
// BM=128, BN=64, BK=16, TM=8, TN=4, 256 threads.
// MODE 0: C = AB^T + bias[n]
// MODE 2: C[(b*TT+t)*N+n] = tanh(AB^T + bias[n]) with row m = t*BB + b (decode)
template <int MODE>
__global__ void __launch_bounds__(256)
gemm_nt(const float* __restrict__ A, const float* __restrict__ Bm,
        float* __restrict__ C, int M, int N, int K,
        const float* __restrict__ bias) {
    constexpr int BM = 128, BN = 64, BK = 16;
    __shared__ float As[BK][BM + 4];
    __shared__ float Bs[BK][BN + 4];

    const int tid = threadIdx.x;
    const int tx = tid & 15;        // 0..15 -> 4 cols each
    const int ty = tid >> 4;        // 0..15 -> 8 rows each
    const int row0 = blockIdx.y * BM;
    const int col0 = blockIdx.x * BN;

    float acc[8][4];
#pragma unroll
    for (int i = 0; i < 8; i++)
#pragma unroll
        for (int j = 0; j < 4; j++) acc[i][j] = 0.0f;

    for (int k0 = 0; k0 < K; k0 += BK) {
        // A fill: 128x16 = 512 float4, 2 per thread
#pragma unroll
        for (int i = tid; i < BM * BK / 4; i += 256) {
            int r = i >> 2, c4 = (i & 3) << 2;
            float4 v = *(const float4*)(A + (size_t)(row0 + r) * K + k0 + c4);
            As[c4 + 0][r] = v.x; As[c4 + 1][r] = v.y;
            As[c4 + 2][r] = v.z; As[c4 + 3][r] = v.w;
        }
        // B fill: 64x16 = 256 float4, 1 per thread
        {
            int i = tid;
            int r = i >> 2, c4 = (i & 3) << 2;
            float4 v = *(const float4*)(Bm + (size_t)(col0 + r) * K + k0 + c4);
            Bs[c4 + 0][r] = v.x; Bs[c4 + 1][r] = v.y;
            Bs[c4 + 2][r] = v.z; Bs[c4 + 3][r] = v.w;
        }
        __syncthreads();
#pragma unroll
        for (int k = 0; k < BK; k++) {
            float4 a0 = *(const float4*)&As[k][ty * 8 + 0];
            float4 a1 = *(const float4*)&As[k][ty * 8 + 4];
            float4 bv = *(const float4*)&Bs[k][tx * 4];
            float a[8] = {a0.x, a0.y, a0.z, a0.w, a1.x, a1.y, a1.z, a1.w};
            float b[4] = {bv.x, bv.y, bv.z, bv.w};
#pragma unroll
            for (int i = 0; i < 8; i++)
#pragma unroll
                for (int j = 0; j < 4; j++) acc[i][j] += a[i] * b[j];
        }
        __syncthreads();
    }

#pragma unroll
    for (int i = 0; i < 8; i++) {
        int m = row0 + ty * 8 + i;
#pragma unroll
        for (int j = 0; j < 4; j++) {
            int n = col0 + tx * 4 + j;
            float v = acc[i][j] + bias[n];
            if (MODE == 0) {
                C[(size_t)m * N + n] = v;
            } else {
                int t = m / BB;
                int b = m % BB;
                C[((size_t)b * TT + t) * N + n] = tanhf(v);
            }
        }
    }
}

// ---------------- grid-wide barrier -----------------------------------------
__device__ __forceinline__ void grid_bar() {
    __syncthreads();
    if (threadIdx.x == 0) {
        __threadfence();
        unsigned int arr = atomicAdd(&g_barrier, 1u);
        unsigned int target = arr - (arr % NBLK) + NBLK;
        while (*(volatile unsigned int*)&g_barrier < target) __nanosleep(20);
    }
    __syncthreads();
}

// ---------------- persistent recurrence kernel -------------------------------
// 128 blocks x 256 threads. Per step:
//   Phase A: hg = h_prev @ W_hh^T   (each block: 128 x 24 tile, K=1024)
//   Phase B: gates + fractional memory, write h_new to ring + Hall
__global__ void __launch_bounds__(NTHR, 1)
recurrence_kernel(const float* __restrict__ W_hh, const float* __restrict__ b_hh) {
    const int tid = threadIdx.x;
    const int blk = blockIdx.x;
    const int tx = tid & 7;     // 0..7 -> 3 cols each
    const int ty = tid >> 3;    // 0..31 -> 4 rows each
    const int col0 = blk * 24;

    __shared__ float As[16][132];   // 132*4 = 528 bytes/row, 16B aligned
    __shared__ float Bs[16][28];

    for (int t = 0; t < TT; t++) {
        const float* hprev = g_ring + (size_t)((t + KK - 1) & (KK - 1)) * BB * HH;

        float acc[4][3];
#pragma unroll
        for (int i = 0; i < 4; i++)
#pragma unroll
            for (int j = 0; j < 3; j++) acc[i][j] = 0.0f;

        for (int k0 = 0; k0 < HH; k0 += 16) {
            // A fill: 128 rows x 16 k = 512 float4 (2/thread), ring -> bypass L1
#pragma unroll
            for (int i = tid; i < 512; i += NTHR) {
                int r = i >> 2, c4 = (i & 3) << 2;
                float4 v = __ldcg((const float4*)(hprev + (size_t)r * HH + k0 + c4));
                As[c4 + 0][r] = v.x; As[c4 + 1][r] = v.y;
                As[c4 + 2][r] = v.z; As[c4 + 3][r] = v.w;
            }
            // B fill: 24 rows x 16 k = 96 float4
            if (tid < 96) {
                int r = tid >> 2, c4 = (tid & 3) << 2;
                float4 v = *(const float4*)(W_hh + (size_t)(col0 + r) * HH + k0 + c4);
                Bs[c4 + 0][r] = v.x; Bs[c4 + 1][r] = v.y;
                Bs[c4 + 2][r] = v.z; Bs[c4 + 3][r] = v.w;
            }
            __syncthreads();
#pragma unroll
            for (int k = 0; k < 16; k++) {
                float4 av = *(const float4*)&As[k][ty << 2];
                float b0 = Bs[k][tx * 3 + 0];
                float b1 = Bs[k][tx * 3 + 1];
                float b2 = Bs[k][tx * 3 + 2];
                acc[0][0] += av.x * b0; acc[0][1] += av.x * b1; acc[0][2] += av.x * b2;
                acc[1][0] += av.y * b0; acc[1][1] += av.y * b1; acc[1][2] += av.y * b2;
                acc[2][0] += av.z * b0; acc[2][1] += av.z * b1; acc[2][2] += av.z * b2;
                acc[3][0] += av.w * b0; acc[3][1] += av.w * b1; acc[3][2] += av.w * b2;
            }
            __syncthreads();
        }
        // store hg tile
#pragma unroll
        for (int i = 0; i < 4; i++) {
            int m = (ty << 2) + i;
#pragma unroll
            for (int j = 0; j < 3; j++)
                g_hg[(size_t)m * G3 + col0 + tx * 3 + j] = acc[i][j];
        }

        grid_bar();  // hg complete

        // Phase B: 131072 elements over 32768 threads -> 4 each
        for (int e = blk * NTHR + tid; e < BB * HH; e += NBLK * NTHR) {
            int b = e >> 10;
            int h = e & 1023;
            const float* xrow = g_xg + ((size_t)b * TT + t) * G3;
            float xz = xrow[h];
            float xr = xrow[HH + h];
            float xn = xrow[2 * HH + h];

            const float* hrow = g_hg + (size_t)b * G3;
            float hz = __ldcg(hrow + h) + b_hh[h];
            float hr = __ldcg(hrow + HH + h) + b_hh[HH + h];
            float hn = __ldcg(hrow + 2 * HH + h) + b_hh[2 * HH + h];

            float z = 1.0f / (1.0f + expf(-(xz + hz)));
            float r = 1.0f / (1.0f + expf(-(xr + hr)));
            float n = tanhf(xn + r * hn);

            // hbuf[k] = h_{t-32+k} lives in ring slot (t+k) & 31
            float mem = 0.0f;
#pragma unroll
            for (int k = 0; k < KK; k++) {
                int s = (t + k) & (KK - 1);
                mem += g_w[k * HH + h] * __ldcg(&g_ring[((size_t)s * BB + b) * HH + h]);
            }

            float hnew = z * n - mem;
            g_ring[((size_t)(t & (KK - 1)) * BB + b) * HH + h] = hnew;
            g_Hall[((size_t)t * BB + b) * HH + h] = hnew;
        }

        grid_bar();  // h_new complete
    }
}

// ---------------- launch ------------------------------------------------------
extern "C" void kernel_launch(void* const* d_in, const int* in_sizes, int n_in,
                              void* d_out, int out_size) {
    const float* input_seq = (const float*)d_in[0];  // (B,T,I)
    const float* mem_para  = (const float*)d_in[1];  // (H,)
    const float* W_ih      = (const float*)d_in[2];  // (3H,I)
    const float* W_hh      = (const float*)d_in[3];  // (3H,H)
    const float* b_ih      = (const float*)d_in[4];  // (3H,)
    const float* b_hh      = (const float*)d_in[5];  // (3H,)
    const float* W_out     = (const float*)d_in[6];  // (O,H)
    const float* b_out     = (const float*)d_in[7];  // (O,)
    float* out = (float*)d_out;

    float *xg, *Hall, *ring;
    cudaGetSymbolAddress((void**)&xg, g_xg);
    cudaGetSymbolAddress((void**)&Hall, g_Hall);
    cudaGetSymbolAddress((void**)&ring, g_ring);

    // 1. lag weights
    compute_w_kernel<<<1, 1024>>>(mem_para);

    // 2. zero ring + reset barrier
    init_kernel<<<1024, 256>>>();

    // 3. input projections: xg(B,T,3H) = input_seq(65536x512) @ W_ih^T + b_ih
    {
        dim3 grid(G3 / 64, (BB * TT) / 128);
        gemm_nt<0><<<grid, 256>>>(input_seq, W_ih, xg, BB * TT, G3, II, b_ih);
    }

    // 4. sequential recurrence: ONE persistent kernel, 512 steps inside
    recurrence_kernel<<<NBLK, NTHR>>>(W_hh, b_hh);

    // 5. decode: out(B,T,O) = tanh(Hall(65536x1024) @ W_out^T + b_out), row remap
    {
        dim3 grid(OO / 64, (TT * BB) / 128);
        gemm_nt<2><<<grid, 256>>>(Hall, W_out, out, TT * BB, OO, HH, b_out);
    }

    // 6. final hbuf: ring slot j holds h_{480+j} (512 % 32 == 0) -> direct copy
    size_t dec_elems = (size_t)BB * TT * OO;
    size_t hbuf_elems = (size_t)KK * BB * HH;
    if ((size_t)out_size >= dec_elems + hbuf_elems) {
        copy_kernel<<<1024, 256>>>(ring, out + dec_elems, hbuf_elems);
    }
}

// round 5
// speedup vs baseline: 2.2652x; 2.2652x over previous
#include <cuda_runtime.h>
#include <cuda_bf16.h>
#include <cstdint>

#define TT 512
#define BB 128
#define II 512
#define HH 1024
#define OO 512
#define KK 32
#define G3 (3 * HH)
#define NBLK 96
#define NTHR 256
#define NWCOL 32            // output cols per block = 3072/96
#define KC 64               // K-chunk in bf16 elems
#define NCHUNK (HH / KC)    // 16

// ---------------- smem layout (dynamic, bytes) --------------------------------
// A chunk buffer: 128 rows x 64 bf16, row stride 144B (padded) = 18432 B per hi/lo
#define A_ROWB 144
#define A_HL   18432
#define A_BUF  36864                       // hi + lo
#define SM_W   (2 * A_BUF)                 // 73728
#define W_ROWB 2064                        // 1032 bf16 padded row
#define W_HL   (32 * W_ROWB)               // 66048
#define SMEM_BYTES (SM_W + 2 * W_HL)       // 205824

// ---------------- scratch (static device globals; allocation-free) ----------
__device__ float g_xg[(size_t)BB * TT * G3];     // (B,T,3H)
__device__ float g_Hall[(size_t)TT * BB * HH];   // (T,B,H)
__device__ float g_ring[(size_t)KK * BB * HH];   // fp32 ring (fractional memory)
__device__ float g_hg[(size_t)BB * G3];          // per-step gate GEMM output
__device__ float g_w[KK * HH];                   // flipped lag weights
__device__ __nv_bfloat16 g_hhi[(size_t)BB * HH]; // h_prev bf16 hi
__device__ __nv_bfloat16 g_hlo[(size_t)BB * HH]; // h_prev bf16 lo (residual)
__device__ unsigned int g_barrier;

// ---------------- PTX helpers ------------------------------------------------
__device__ __forceinline__ uint32_t smem_u32(const void* p) {
    uint32_t a;
    asm("{ .reg .u64 t; cvta.to.shared.u64 t, %1; cvt.u32.u64 %0, t; }" : "=r"(a) : "l"(p));
    return a;
}
__device__ __forceinline__ void cpa16(uint32_t dst, const void* src) {
    asm volatile("cp.async.cg.shared.global [%0], [%1], 16;" :: "r"(dst), "l"(src));
}
__device__ __forceinline__ void cpa_commit() { asm volatile("cp.async.commit_group;"); }
template <int N> __device__ __forceinline__ void cpa_wait() {
    asm volatile("cp.async.wait_group %0;" :: "n"(N));
}
__device__ __forceinline__ void ldsm_x4(uint32_t& r0, uint32_t& r1, uint32_t& r2,
                                        uint32_t& r3, uint32_t addr) {
    asm volatile("ldmatrix.sync.aligned.m8n8.x4.shared.b16 {%0,%1,%2,%3}, [%4];"
                 : "=r"(r0), "=r"(r1), "=r"(r2), "=r"(r3) : "r"(addr));
}
__device__ __forceinline__ void ldsm_x2(uint32_t& r0, uint32_t& r1, uint32_t addr) {
    asm volatile("ldmatrix.sync.aligned.m8n8.x2.shared.b16 {%0,%1}, [%2];"
                 : "=r"(r0), "=r"(r1) : "r"(addr));
}
__device__ __forceinline__ void mma_bf16(float* c, uint32_t a0, uint32_t a1, uint32_t a2,
                                         uint32_t a3, uint32_t b0, uint32_t b1) {
    asm volatile(
        "mma.sync.aligned.m16n8k16.row.col.f32.bf16.bf16.f32 "
        "{%0,%1,%2,%3}, {%4,%5,%6,%7}, {%8,%9}, {%0,%1,%2,%3};"
        : "+f"(c[0]), "+f"(c[1]), "+f"(c[2]), "+f"(c[3])
        : "r"(a0), "r"(a1), "r"(a2), "r"(a3), "r"(b0), "r"(b1));
}

// ---------------- small prep kernels ----------------------------------------
__global__ void compute_w_kernel(const float* __restrict__ mem_para) {
    int h = blockIdx.x * blockDim.x + threadIdx.x;
    if (h >= HH) return;
    float d = 0.5f / (1.0f + expf(-mem_para[h]));
    float cum = 1.0f;
    for (int k = 0; k < KK; k++) {
        cum *= ((float)k - d) / ((float)k + 1.0f);
        g_w[(KK - 1 - k) * HH + h] = cum;
    }
}

__global__ void init_kernel() {
    size_t n = (size_t)KK * BB * HH;
    size_t stride = (size_t)gridDim.x * blockDim.x;
    for (size_t i = (size_t)blockIdx.x * blockDim.x + threadIdx.x; i < n; i += stride)
        g_ring[i] = 0.0f;
    size_t nh = (size_t)BB * HH;
    for (size_t i = (size_t)blockIdx.x * blockDim.x + threadIdx.x; i < nh; i += stride) {
        g_hhi[i] = __float2bfloat16(0.0f);
        g_hlo[i] = __float2bfloat16(0.0f);
    }
    if (blockIdx.x == 0 && threadIdx.x == 0) g_barrier = 0u;
}

__global__ void copy_kernel(const float* __restrict__ src, float* __restrict__ dst, size_t n) {
    size_t stride = (size_t)gridDim.x * blockDim.x;
    for (size_t i = (size_t)blockIdx.x * blockDim.x + threadIdx.x; i < n; i += stride)
        dst[i] = src[i];
}

// ---------------- fp32 NT GEMM (xg + decode) ---------------------------------
template <int MODE>
__global__ void __launch_bounds__(256)
gemm_nt(const float* __restrict__ A, const float* __restrict__ Bm,
        float* __restrict__ C, int M, int N, int K,
        const float* __restrict__ bias) {
    constexpr int BM = 128, BN = 64, BK = 16;
    __shared__ float As[BK][BM + 4];
    __shared__ float Bs[BK][BN + 4];

    const int tid = threadIdx.x;
    const int tx = tid & 15;
    const int ty = tid >> 4;
    const int row0 = blockIdx.y * BM;
    const int col0 = blockIdx.x * BN;

    float acc[8][4];
#pragma unroll
    for (int i = 0; i < 8; i++)
#pragma unroll
        for (int j = 0; j < 4; j++) acc[i][j] = 0.0f;

    for (int k0 = 0; k0 < K; k0 += BK) {
#pragma unroll
        for (int i = tid; i < BM * BK / 4; i += 256) {
            int r = i >> 2, c4 = (i & 3) << 2;
            float4 v = *(const float4*)(A + (size_t)(row0 + r) * K + k0 + c4);
            As[c4 + 0][r] = v.x; As[c4 + 1][r] = v.y;
            As[c4 + 2][r] = v.z; As[c4 + 3][r] = v.w;
        }
        {
            int r = tid >> 2, c4 = (tid & 3) << 2;
            float4 v = *(const float4*)(Bm + (size_t)(col0 + r) * K + k0 + c4);
            Bs[c4 + 0][r] = v.x; Bs[c4 + 1][r] = v.y;
            Bs[c4 + 2][r] = v.z; Bs[c4 + 3][r] = v.w;
        }
        __syncthreads();
#pragma unroll
        for (int k = 0; k < BK; k++) {
            float4 a0 = *(const float4*)&As[k][ty * 8 + 0];
            float4 a1 = *(const float4*)&As[k][ty * 8 + 4];
            float4 bv = *(const float4*)&Bs[k][tx * 4];
            float a[8] = {a0.x, a0.y, a0.z, a0.w, a1.x, a1.y, a1.z, a1.w};
            float b[4] = {bv.x, bv.y, bv.z, bv.w};
#pragma unroll
            for (int i = 0; i < 8; i++)
#pragma unroll
                for (int j = 0; j < 4; j++) acc[i][j] += a[i] * b[j];
        }
        __syncthreads();
    }
#pragma unroll
    for (int i = 0; i < 8; i++) {
        int m = row0 + ty * 8 + i;
#pragma unroll
        for (int j = 0; j < 4; j++) {
            int n = col0 + tx * 4 + j;
            float v = acc[i][j] + bias[n];
            if (MODE == 0) {
                C[(size_t)m * N + n] = v;
            } else {
                int t = m / BB;
                int b = m % BB;
                C[((size_t)b * TT + t) * N + n] = tanhf(v);
            }
        }
    }
}

// ---------------- grid-wide barrier ------------------------------------------
__device__ __forceinline__ void grid_bar() {
    __syncthreads();
    if (threadIdx.x == 0) {
        __threadfence();
        unsigned int arr = atomicAdd(&g_barrier, 1u);
        unsigned int target = arr - (arr % NBLK) + NBLK;
        while (*(volatile unsigned int*)&g_barrier < target) __nanosleep(20);
    }
    __syncthreads();
}

// ---------------- persistent HMMA recurrence ----------------------------------
// 96 blocks x 256 threads (8 warps, 4m x 2n). Block tile: M=128, N=32, K=1024.
// Warp tile 32x16: 2x2 m16n8k16 tiles, 3-term bf16 split.
__global__ void __launch_bounds__(NTHR, 1)
recurrence_kernel(const float* __restrict__ W_hh, const float* __restrict__ b_hh) {
    extern __shared__ char smem[];
    const uint32_t sb = smem_u32(smem);
    const int tid = threadIdx.x;
    const int wid = tid >> 5;
    const int lane = tid & 31;
    const int blk = blockIdx.x;
    const int col0 = blk * NWCOL;
    const int wm = wid & 3;      // m-warp: rows wm*32..+31
    const int wn = wid >> 2;     // n-warp: cols wn*16..+15

    // ---- W slice preload: fp32 -> bf16 hi/lo, padded row-major (n,k) --------
    for (int idx = tid; idx < NWCOL * HH; idx += NTHR) {
        int r = idx >> 10;
        int k = idx & 1023;
        float w = W_hh[(size_t)(col0 + r) * HH + k];
        __nv_bfloat16 hi = __float2bfloat16(w);
        __nv_bfloat16 lo = __float2bfloat16(w - __bfloat162float(hi));
        *(__nv_bfloat16*)(smem + SM_W + r * W_ROWB + k * 2) = hi;
        *(__nv_bfloat16*)(smem + SM_W + W_HL + r * W_ROWB + k * 2) = lo;
    }
    __syncthreads();

    // per-lane ldmatrix address components
    const int a_row_l = (lane & 7) + ((lane >> 3) & 1) * 8;   // + m_base
    const int a_col_l = (lane >> 4) * 8;                      // + kstep*16
    const int b_row_l = wn * 16 + (lane & 7);                 // + j*8
    const int b_col_l = ((lane >> 3) & 1) * 8;                // + global k
    const uint32_t wbase_hi = sb + SM_W + b_row_l * W_ROWB + b_col_l * 2;
    const uint32_t wbase_lo = wbase_hi + W_HL;

    for (int t = 0; t < TT; t++) {
        // -------- phase A: hg = h_prev @ W_hh^T via HMMA ----------------------
        float acc[2][2][4];
#pragma unroll
        for (int i = 0; i < 2; i++)
#pragma unroll
            for (int j = 0; j < 2; j++)
#pragma unroll
                for (int q = 0; q < 4; q++) acc[i][j][q] = 0.0f;

        // preload chunk 0 into buf 0
        {
            const char* hhi = (const char*)g_hhi;
            const char* hlo = (const char*)g_hlo;
#pragma unroll
            for (int jj = 0; jj < 8; jj++) {
                int g = tid + jj * NTHR;
                int arr = g >> 10;
                int w = g & 1023;
                int row = w >> 3, piece = w & 7;
                uint32_t dst = sb + arr * A_HL + row * A_ROWB + piece * 16;
                const char* src = (arr ? hlo : hhi) + (size_t)row * (HH * 2) + piece * 16;
                cpa16(dst, src);
            }
            cpa_commit();
        }

        for (int c = 0; c < NCHUNK; c++) {
            if (c + 1 < NCHUNK) {
                const char* hhi = (const char*)g_hhi;
                const char* hlo = (const char*)g_hlo;
                uint32_t abase = sb + ((c + 1) & 1) * A_BUF;
#pragma unroll
                for (int jj = 0; jj < 8; jj++) {
                    int g = tid + jj * NTHR;
                    int arr = g >> 10;
                    int w = g & 1023;
                    int row = w >> 3, piece = w & 7;
                    uint32_t dst = abase + arr * A_HL + row * A_ROWB + piece * 16;
                    const char* src = (arr ? hlo : hhi) +
                                      (size_t)row * (HH * 2) + (c + 1) * (KC * 2) + piece * 16;
                    cpa16(dst, src);
                }
                cpa_commit();
                cpa_wait<1>();
            } else {
                cpa_wait<0>();
            }
            __syncthreads();   // chunk c resident for all warps

            uint32_t abuf = sb + (c & 1) * A_BUF;
#pragma unroll
            for (int s = 0; s < 4; s++) {
                int kg = c * KC + s * 16;  // global k for B
                // A fragments (hi & lo) for 2 m-tiles
                uint32_t ah[2][4], al[2][4];
#pragma unroll
                for (int i = 0; i < 2; i++) {
                    int mrow = wm * 32 + i * 16 + a_row_l;
                    uint32_t aoff = mrow * A_ROWB + (s * 16 + a_col_l) * 2;
                    ldsm_x4(ah[i][0], ah[i][1], ah[i][2], ah[i][3], abuf + aoff);
                    ldsm_x4(al[i][0], al[i][1], al[i][2], al[i][3], abuf + A_HL + aoff);
                }
                // B fragments (hi & lo) for 2 n-tiles
                uint32_t bh[2][2], bl[2][2];
#pragma unroll
                for (int j = 0; j < 2; j++) {
                    uint32_t boff = j * 8 * W_ROWB + kg * 2;
                    ldsm_x2(bh[j][0], bh[j][1], wbase_hi + boff);
                    ldsm_x2(bl[j][0], bl[j][1], wbase_lo + boff);
                }
#pragma unroll
                for (int i = 0; i < 2; i++)
#pragma unroll
                    for (int j = 0; j < 2; j++) {
                        mma_bf16(acc[i][j], ah[i][0], ah[i][1], ah[i][2], ah[i][3],
                                 bh[j][0], bh[j][1]);
                        mma_bf16(acc[i][j], ah[i][0], ah[i][1], ah[i][2], ah[i][3],
                                 bl[j][0], bl[j][1]);
                        mma_bf16(acc[i][j], al[i][0], al[i][1], al[i][2], al[i][3],
                                 bh[j][0], bh[j][1]);
                    }
            }
            __syncthreads();   // compute on buf c done before buf is refilled
        }

        // -------- epilogue: acc -> g_hg --------------------------------------
        {
            int qrow = lane >> 2;          // 0..7
            int qcol = (lane & 3) * 2;     // 0,2,4,6
#pragma unroll
            for (int i = 0; i < 2; i++) {
                int m0 = wm * 32 + i * 16 + qrow;
#pragma unroll
                for (int j = 0; j < 2; j++) {
                    int n0 = col0 + wn * 16 + j * 8 + qcol;
                    *(float2*)(g_hg + (size_t)m0 * G3 + n0) =
                        make_float2(acc[i][j][0], acc[i][j][1]);
                    *(float2*)(g_hg + (size_t)(m0 + 8) * G3 + n0) =
                        make_float2(acc[i][j][2], acc[i][j][3]);
                }
            }
        }

        grid_bar();  // hg complete everywhere

        // -------- phase B: gates + fractional memory -------------------------
        for (int e = blk * NTHR + tid; e < BB * HH; e += NBLK * NTHR) {
            int b = e >> 10;
            int h = e & 1023;
            const float* xrow = g_xg + ((size_t)b * TT + t) * G3;
            float xz = xrow[h];
            float xr = xrow[HH + h];
            float xn = xrow[2 * HH + h];

            const float* hrow = g_hg + (size_t)b * G3;
            float hz = __ldcg(hrow + h) + b_hh[h];
            float hr = __ldcg(hrow + HH + h) + b_hh[HH + h];
            float hn = __ldcg(hrow + 2 * HH + h) + b_hh[2 * HH + h];

            float z = 1.0f / (1.0f + expf(-(xz + hz)));
            float r = 1.0f / (1.0f + expf(-(xr + hr)));
            float n = tanhf(xn + r * hn);

            float mem = 0.0f;
#pragma unroll
            for (int k = 0; k < KK; k++) {
                int s = (t + k) & (KK - 1);
                mem += g_w[k * HH + h] * __ldcg(&g_ring[((size_t)s * BB + b) * HH + h]);
            }

            float hnew = z * n - mem;
            g_ring[((size_t)(t & (KK - 1)) * BB + b) * HH + h] = hnew;
            g_Hall[((size_t)t * BB + b) * HH + h] = hnew;
            __nv_bfloat16 hb = __float2bfloat16(hnew);
            g_hhi[e] = hb;
            g_hlo[e] = __float2bfloat16(hnew - __bfloat162float(hb));
        }

        grid_bar();  // h_new (fp32 + bf16 hi/lo) complete everywhere
    }
}

// ---------------- launch ------------------------------------------------------
extern "C" void kernel_launch(void* const* d_in, const int* in_sizes, int n_in,
                              void* d_out, int out_size) {
    const float* input_seq = (const float*)d_in[0];
    const float* mem_para  = (const float*)d_in[1];
    const float* W_ih      = (const float*)d_in[2];
    const float* W_hh      = (const float*)d_in[3];
    const float* b_ih      = (const float*)d_in[4];
    const float* b_hh      = (const float*)d_in[5];
    const float* W_out     = (const float*)d_in[6];
    const float* b_out     = (const float*)d_in[7];
    float* out = (float*)d_out;

    static bool attr_set = false;
    if (!attr_set) {
        cudaFuncSetAttribute(recurrence_kernel,
                             cudaFuncAttributeMaxDynamicSharedMemorySize, SMEM_BYTES);
        attr_set = true;
    }

    float *xg, *Hall, *ring;
    cudaGetSymbolAddress((void**)&xg, g_xg);
    cudaGetSymbolAddress((void**)&Hall, g_Hall);
    cudaGetSymbolAddress((void**)&ring, g_ring);

    compute_w_kernel<<<1, 1024>>>(mem_para);
    init_kernel<<<1024, 256>>>();

    {   // xg(B,T,3H) = input_seq @ W_ih^T + b_ih
        dim3 grid(G3 / 64, (BB * TT) / 128);
        gemm_nt<0><<<grid, 256>>>(input_seq, W_ih, xg, BB * TT, G3, II, b_ih);
    }

    recurrence_kernel<<<NBLK, NTHR, SMEM_BYTES>>>(W_hh, b_hh);

    {   // decode
        dim3 grid(OO / 64, (TT * BB) / 128);
        gemm_nt<2><<<grid, 256>>>(Hall, W_out, out, TT * BB, OO, HH, b_out);
    }

    size_t dec_elems = (size_t)BB * TT * OO;
    size_t hbuf_elems = (size_t)KK * BB * HH;
    if ((size_t)out_size >= dec_elems + hbuf_elems) {
        copy_kernel<<<1024, 256>>>(ring, out + dec_elems, hbuf_elems);
    }
}